// round 17
// baseline (speedup 1.0000x reference)
#include <cuda_runtime.h>
#include <cuda_fp16.h>
#include <math.h>
#include <stdint.h>

// Problem constants
static constexpr int kB  = 64;      // batch
static constexpr int kT  = 1024;    // time steps
static constexpr int kF  = 512;     // input features
static constexpr int kU  = 1024;    // hidden units
static constexpr int k4U = 4096;    // 4*U
static constexpr int kC  = 1000;    // classes

static constexpr int NCTA = 128;    // persistent CTAs (1/SM)
static constexpr int NTHR = 256;    // 8 warps: 0-3 consumers (LSTM), 4-7 producers (xz)

// SMEM layout (u32 units within dynamic smem)
static constexpr int OFF_WRF   = 0;        // Wr fp16 fragments: 16384 u32 (64 KB)
static constexpr int OFF_WKF   = 16384;    // Wk fp16 frags: 4096 uint2 = 8192 u32 (32 KB)
static constexpr int OFF_RING  = 24576;    // xz ring: 4 stages x 64 x 34 fp32 = 8704 u32
static constexpr int OFF_BIAS  = 33280;    // 32 fp32
static constexpr int OFF_FLAGS = 33312;    // pflag[4], lcnt
static constexpr int SMEM_U32  = 33320;    // 133280 bytes
// tail phases reuse fsm[0..32832) for de-permuted h / softmax reduction

// Scratch (device globals: allocation-free per harness rules)
// h ping-pong, fp16, permuted into m16n8k16 A-fragment order (see R5 comment)
__device__ uint32_t g_h[2 * 32768];
// Per-group monotonic warp-arrival counters (64 arrivals/group/step)
__device__ unsigned g_cnt[8 * 32];
// logits (pre-bias), written by persistent kernel head phase
__device__ float    g_logits[64 * kC];
// device-wide completion counter for in-kernel softmax
__device__ unsigned g_done;

__device__ __forceinline__ uint32_t pack_f16(float lo, float hi) {
    uint32_t r;
    asm("cvt.rn.f16x2.f32 %0, %1, %2;" : "=r"(r) : "f"(hi), "f"(lo));
    return r;
}
__device__ __forceinline__ float tanh_fast(float x) {
    float r;
    asm("tanh.approx.f32 %0, %1;" : "=f"(r) : "f"(x));
    return r;
}
__device__ __forceinline__ float sigmoid_fast(float x) {
    return 1.f / (1.f + __expf(-x));
}
__device__ __forceinline__ void mma_f16(float c[4], uint32_t a0, uint32_t a1,
                                        uint32_t a2, uint32_t a3,
                                        uint32_t b0, uint32_t b1) {
    asm volatile(
        "mma.sync.aligned.m16n8k16.row.col.f32.f16.f16.f32 "
        "{%0,%1,%2,%3},{%4,%5,%6,%7},{%8,%9},{%0,%1,%2,%3};"
        : "+f"(c[0]), "+f"(c[1]), "+f"(c[2]), "+f"(c[3])
        : "r"(a0), "r"(a1), "r"(a2), "r"(a3), "r"(b0), "r"(b1));
}
__device__ __forceinline__ void bar_named(int id, int cnt) {
    asm volatile("bar.sync %0, %1;" :: "r"(id), "r"(cnt) : "memory");
}
__device__ __forceinline__ unsigned ld_acq(const unsigned* p) {
    unsigned v;
    asm volatile("ld.acquire.gpu.u32 %0, [%1];" : "=r"(v) : "l"(p) : "memory");
    return v;
}
// Warp-cooperative group-counter poll. Lanes 0-7 own one group counter each.
__device__ __forceinline__ unsigned poll_groups(int lane, unsigned tgt,
                                                unsigned rdy) {
    unsigned ok = 1u;
    if (lane < 8 && !((rdy >> lane) & 1u)) {
        unsigned v = ld_acq(&g_cnt[lane * 32]);
        ok = (v >= tgt) ? 1u : 0u;
    }
    return __ballot_sync(0xffffffffu, ok != 0u);
}

// ---------------------------------------------------------------------------
// Kernel 0: reset (h buffer 0, counters). Fast: ~33K u32.
// ---------------------------------------------------------------------------
__global__ void reset_kernel() {
    int idx = blockIdx.x * blockDim.x + threadIdx.x;
    if (idx == 0) g_done = 0u;
    if (idx < 8 * 32) g_cnt[idx] = 0u;
    for (int i = idx; i < 32768; i += gridDim.x * blockDim.x) g_h[i] = 0u;
}

// ---------------------------------------------------------------------------
// Kernel 1: fused persistent LSTM + in-kernel logits + in-kernel softmax.
// Warps 0-3: recurrence mma + gates; warps 4-7: per-step xz (full K=512,
// x converted fp32->fp16 INLINE from its native layout) into a 4-deep SMEM
// ring. Warp-granular publish, JIT group polling. After the t-loop: logits
// head (classes [8*cta,8*cta+8)), then device-wide barrier and CTAs 0-63
// softmax their batch row straight into d_out.
// ---------------------------------------------------------------------------
extern __shared__ uint32_t fsm[];

__global__ __launch_bounds__(NTHR, 1) void lstm_fused(
    const float* __restrict__ x, const float* __restrict__ Wr,
    const float* __restrict__ Wk, const float* __restrict__ bias,
    const float* __restrict__ Wd, const float* __restrict__ bd,
    float* __restrict__ out) {
    uint32_t*      Wr_f  = fsm + OFF_WRF;
    uint2*         Wk_f  = (uint2*)(fsm + OFF_WKF);
    float*         ring  = (float*)(fsm + OFF_RING);     // [4][64][34]
    float*         bia_s = (float*)(fsm + OFF_BIAS);
    volatile int*  pflag = (volatile int*)(fsm + OFF_FLAGS);      // [4]
    int*           lcnt  = (int*)(fsm + OFF_FLAGS + 4);           // ring credits

    const int tid = threadIdx.x;
    const int wid = tid >> 5, lid = tid & 31;
    const int u_base = blockIdx.x * 8;
    const int my_group = blockIdx.x >> 4;

    // ---- cooperative init (all 8 warps) ----
    // Wr fp16 fragments (16384 u32)
    for (int i = 0; i < 64; i++) {
        int lin = tid + i * NTHR;
        int reg = lin & 1;
        int ll  = (lin >> 1) & 31;
        int kcg = (lin >> 6) & 63;
        int q   = (lin >> 12) & 3;
        int lg = ll >> 2, lq = ll & 3;
        int k  = kcg * 16 + 2 * lq + 8 * reg;
        int col = q * kU + u_base + lg;
        float v0 = Wr[(size_t)k * k4U + col];
        float v1 = Wr[(size_t)(k + 1) * k4U + col];
        Wr_f[((q * 64 + kcg) * 32 + ll) * 2 + reg] = pack_f16(v0, v1);
    }
    // Wk fp16 fragments (4096 uint2): all 32 kcg
    for (int i = 0; i < 16; i++) {
        int lin = tid + i * NTHR;
        int lane = lin & 31;
        int nt   = (lin >> 5) & 3;
        int kcg  = lin >> 7;
        int gcol = nt * kU + u_base + (lane >> 2);
        int k2   = kcg * 16 + 2 * (lane & 3);
        uint2 bv;
        bv.x = pack_f16(Wk[(size_t)k2 * k4U + gcol],
                        Wk[(size_t)(k2 + 1) * k4U + gcol]);
        bv.y = pack_f16(Wk[(size_t)(k2 + 8) * k4U + gcol],
                        Wk[(size_t)(k2 + 9) * k4U + gcol]);
        Wk_f[(kcg * 4 + nt) * 32 + lane] = bv;
    }
    if (tid < 32) bia_s[tid] = bias[(tid >> 3) * kU + u_base + (tid & 7)];
    if (tid < 4) pflag[tid] = 0;
    if (tid == 0) *lcnt = 0;
    __syncthreads();

    if (wid >= 4) {
        // ========== PRODUCER (warps 4-7): xz full K, inline x->fp16 ==========
        const int pw = wid - 4;              // M-subtile (16 batch rows)
        const int rr = lid >> 2;             // row within subtile quad group
        const int r  = pw * 16 + rr;
        const int kq = 2 * (lid & 3);
        const int cl = 2 * (lid & 3);
        const float* xr0 = x + (size_t)r * kT * kF;        // + tp*kF later
        const float* xr1 = x + (size_t)(r + 8) * kT * kF;
        for (int tp = 0; tp < kT; tp++) {
            const int s = tp & 3;
            if (tp >= 4) {
                int sp = 0;
                int tgt = 4 * (tp - 3);
                while (*(volatile int*)lcnt < tgt) {
                    if (++sp > 4) __nanosleep(40);
                }
                __threadfence_block();
            }
            float cacc[4][4];
#pragma unroll
            for (int nt = 0; nt < 4; nt++)
#pragma unroll
                for (int k = 0; k < 4; k++) cacc[nt][k] = 0.f;

            const float* x0 = xr0 + (size_t)tp * kF;
            const float* x1 = xr1 + (size_t)tp * kF;
            // software-pipelined inline conversion (depth 1)
            float2 v00 = *(const float2*)(x0 + kq);
            float2 v10 = *(const float2*)(x1 + kq);
            float2 v01 = *(const float2*)(x0 + kq + 8);
            float2 v11 = *(const float2*)(x1 + kq + 8);
#pragma unroll 4
            for (int kcg = 0; kcg < 32; kcg++) {
                uint32_t a0 = pack_f16(v00.x, v00.y);
                uint32_t a1 = pack_f16(v10.x, v10.y);
                uint32_t a2 = pack_f16(v01.x, v01.y);
                uint32_t a3 = pack_f16(v11.x, v11.y);
                if (kcg < 31) {
                    int k2 = (kcg + 1) * 16 + kq;
                    v00 = *(const float2*)(x0 + k2);
                    v10 = *(const float2*)(x1 + k2);
                    v01 = *(const float2*)(x0 + k2 + 8);
                    v11 = *(const float2*)(x1 + k2 + 8);
                }
#pragma unroll
                for (int nt = 0; nt < 4; nt++) {
                    uint2 bv = Wk_f[(kcg * 4 + nt) * 32 + lid];
                    mma_f16(cacc[nt], a0, a1, a2, a3, bv.x, bv.y);
                }
            }
            // epilogue: bias + ring store
            float* rs = ring + (size_t)s * 64 * 34;
#pragma unroll
            for (int nt = 0; nt < 4; nt++) {
                int col = nt * 8 + cl;
                float bx = bia_s[col], by = bia_s[col + 1];
                float2 lo = make_float2(cacc[nt][0] + bx, cacc[nt][1] + by);
                float2 hi = make_float2(cacc[nt][2] + bx, cacc[nt][3] + by);
                *(float2*)&rs[(r)     * 34 + col] = lo;
                *(float2*)&rs[(r + 8) * 34 + col] = hi;
            }
            __threadfence_block();
            bar_named(3, 128);               // producer warps only
            if (tid == 128) pflag[s] = tp + 1;
        }
    } else {
        // ================= CONSUMER (warps 0-3) =================
        const int w = wid, l = lid;
        const int grp = l >> 2, qd = l & 3;
        const int b0 = w * 16 + grp;         // batch rows b0, b0+8
        const int j0 = 2 * qd;               // units j0, j0+1
        const int kcg_w = blockIdx.x >> 1;
        const int hi_w  = blockIdx.x & 1;

        float cst[4] = {0.f, 0.f, 0.f, 0.f};

        for (int t = 0; t < kT; t++) {
            const uint4* Ag = (const uint4*)(g_h + (size_t)(t & 1) * 32768);
            uint32_t*  hwrt = g_h + (size_t)((t + 1) & 1) * 32768;

            // Group-ready mask: warp-arrival counters, 64 per group per step.
            unsigned tgt = 64u * (unsigned)t;
            unsigned rdy = (t == 0) ? 0xffffffffu : 0u;
            const int g0 = my_group;
            {
                int sp = 0;
                while (!((rdy >> g0) & 1u)) {
                    rdy = poll_groups(l, tgt, rdy);
                    if (!((rdy >> g0) & 1u) && ++sp > 4) __nanosleep(40);
                }
            }

            float acc[4][2][4];
#pragma unroll
            for (int q = 0; q < 4; q++)
#pragma unroll
                for (int p = 0; p < 2; p++)
#pragma unroll
                    for (int k = 0; k < 4; k++) acc[q][p][k] = 0.f;

            uint4 abuf[8];
#pragma unroll
            for (int i = 0; i < 8; i++)
                abuf[i] = __ldcg(Ag + (8 * g0 + i) * 128 + tid);

            for (int ch = 0; ch < 8; ch++) {
                const int g  = (ch + my_group) & 7;
                const int gn = (g + 1) & 7;
                if (ch < 7) {
                    int sp = 0;
                    while (!((rdy >> gn) & 1u)) {
                        rdy = poll_groups(l, tgt, rdy);
                        if (!((rdy >> gn) & 1u) && ++sp > 4) __nanosleep(40);
                    }
                }
#pragma unroll
                for (int k8 = 0; k8 < 8; k8++) {
                    uint4 a = abuf[k8];
                    if (ch < 7) abuf[k8] = __ldcg(Ag + (8 * gn + k8) * 128 + tid);
                    int kcg = 8 * g + k8;
#pragma unroll
                    for (int q = 0; q < 4; q++) {
                        uint2 bv = *(const uint2*)&Wr_f[((q * 64 + kcg) * 32 + l) * 2];
                        mma_f16(acc[q][k8 & 1], a.x, a.y, a.z, a.w, bv.x, bv.y);
                    }
                }
            }

            // xz from SMEM ring
            const int s = t & 3;
            {
                int sp = 0;
                while (pflag[s] < t + 1) { if (++sp > 4) __nanosleep(40); }
            }
            __threadfence_block();
            const float* rs = ring + (size_t)s * 64 * 34;
            float2 xz[2][4];
#pragma unroll
            for (int r2 = 0; r2 < 2; r2++)
#pragma unroll
                for (int q = 0; q < 4; q++)
                    xz[r2][q] = *(const float2*)&rs[(b0 + 8 * r2) * 34 + q * 8 + j0];

            // gate phase (registers only)
#pragma unroll
            for (int r2 = 0; r2 < 2; r2++) {
                float hv[2];
#pragma unroll
                for (int d = 0; d < 2; d++) {
                    int idx = 2 * r2 + d;
                    float zi = acc[0][0][idx] + acc[0][1][idx] + (d ? xz[r2][0].y : xz[r2][0].x);
                    float zf = acc[1][0][idx] + acc[1][1][idx] + (d ? xz[r2][1].y : xz[r2][1].x);
                    float zg = acc[2][0][idx] + acc[2][1][idx] + (d ? xz[r2][2].y : xz[r2][2].x);
                    float zo = acc[3][0][idx] + acc[3][1][idx] + (d ? xz[r2][3].y : xz[r2][3].x);
                    float ig = sigmoid_fast(zi);
                    float fg = sigmoid_fast(zf);
                    float gg = tanh_fast(zg);
                    float og = sigmoid_fast(zo);
                    float cv = fg * cst[idx] + ig * gg;
                    cst[idx] = cv;
                    hv[d] = og * tanh_fast(cv);
                }
                hwrt[(kcg_w * 128 + tid) * 4 + 2 * hi_w + r2] = pack_f16(hv[0], hv[1]);
            }

            // warp-granular publish: h arrival (cross-CTA) + ring credit (CTA)
            __threadfence();
            __syncwarp();
            if (l == 0) {
                atomicAdd(&g_cnt[my_group * 32], 1u);
                atomicAdd_block(lcnt, 1);
            }
        }
    }

    // ================= HEAD: logits for classes [8*cta, 8*cta+8) =============
    __syncthreads();                         // join producer/consumer roles
    {
        unsigned rdy = 0u;
        int sp = 0;
        while (rdy != 0xffffffffu) {
            rdy = poll_groups(lid, 64u * (unsigned)kT, rdy);
            if (rdy != 0xffffffffu && ++sp > 4) __nanosleep(100);
        }
    }
    // Stage h (buffer 0, fp16 permuted) de-permuted into SMEM, row-major with
    // padded stride 513 u32 (bank-conflict-free).
    uint32_t* smem_h = fsm;                  // 64 * 513 = 32832 u32 (< SMEM_U32)
    for (int i = 0; i < 32768 / NTHR; i++) {
        int idx = tid + i * NTHR;
        uint32_t v = __ldcg(&g_h[idx]);      // buffer 0 = h(t=1024)
        int y  = idx >> 2;
        int b  = (((y >> 5) & 3) << 4) | ((idx & 1) << 3) | ((y >> 2) & 7);
        int up = ((y >> 7) << 3) | (((idx >> 1) & 1) << 2) | (y & 3);  // u>>1
        smem_h[b * 513 + up] = v;
    }
    __syncthreads();

    const int c = blockIdx.x * 8 + wid;      // this warp's class
    if (c < kC) {
        const uint32_t* h1 = smem_h + (size_t)lid * 513;        // row lid
        const uint32_t* h2 = smem_h + (size_t)(lid + 32) * 513; // row lid+32
        float a1 = 0.f, a2 = 0.f;
        for (int kb = 0; kb < kU; kb += 32) {
            float wv = __ldg(&Wd[(size_t)(kb + lid) * kC + c]);
#pragma unroll
            for (int j = 0; j < 32; j += 2) {
                float w0 = __shfl_sync(0xffffffffu, wv, j);
                float w1 = __shfl_sync(0xffffffffu, wv, j + 1);
                uint32_t p1 = h1[(kb + j) >> 1];
                uint32_t p2 = h2[(kb + j) >> 1];
                __half2 q1 = *(__half2*)&p1;   // lo = even k
                __half2 q2 = *(__half2*)&p2;
                a1 = fmaf(__low2float(q1),  w0, a1);
                a1 = fmaf(__high2float(q1), w1, a1);
                a2 = fmaf(__low2float(q2),  w0, a2);
                a2 = fmaf(__high2float(q2), w1, a2);
            }
        }
        g_logits[(size_t)lid * kC + c]        = a1;
        g_logits[(size_t)(lid + 32) * kC + c] = a2;
    }

    // ================= SOFTMAX (CTAs 0-63, one batch row each) ==============
    __syncthreads();
    if (tid == 0) {
        __threadfence();
        atomicAdd(&g_done, 1u);
    }
    if (blockIdx.x < 64) {
        if (tid == 0) {
            int sp = 0;
            while (ld_acq(&g_done) < (unsigned)NCTA) {
                if (++sp > 4) __nanosleep(100);
            }
        }
        __syncthreads();

        float* red = (float*)fsm;            // 256 fp32 reduction scratch
        const int b  = blockIdx.x;
        const int j0 = tid * 4;
        const bool active = (j0 < kC);

        float acc[4] = {0.f, 0.f, 0.f, 0.f};
        if (active) {
            float4 v;
            v.x = __ldcg(&g_logits[(size_t)b * kC + j0]);
            v.y = __ldcg(&g_logits[(size_t)b * kC + j0 + 1]);
            v.z = __ldcg(&g_logits[(size_t)b * kC + j0 + 2]);
            v.w = __ldcg(&g_logits[(size_t)b * kC + j0 + 3]);
            float4 bv = *(const float4*)&bd[j0];
            acc[0] = v.x + bv.x; acc[1] = v.y + bv.y;
            acc[2] = v.z + bv.z; acc[3] = v.w + bv.w;
        }

        float m = active ? fmaxf(fmaxf(acc[0], acc[1]), fmaxf(acc[2], acc[3]))
                         : -INFINITY;
        red[tid] = m;
        __syncthreads();
        for (int s = 128; s > 0; s >>= 1) {
            if (tid < s) red[tid] = fmaxf(red[tid], red[tid + s]);
            __syncthreads();
        }
        float mx = red[0];
        __syncthreads();

        float e[4] = {0.f, 0.f, 0.f, 0.f};
        float psum = 0.f;
        if (active) {
#pragma unroll
            for (int cc = 0; cc < 4; cc++) { e[cc] = expf(acc[cc] - mx); psum += e[cc]; }
        }
        red[tid] = psum;
        __syncthreads();
        for (int s = 128; s > 0; s >>= 1) {
            if (tid < s) red[tid] += red[tid + s];
            __syncthreads();
        }
        float inv = 1.f / red[0];
        if (active) {
#pragma unroll
            for (int cc = 0; cc < 4; cc++)
                out[(size_t)b * kC + j0 + cc] = e[cc] * inv;
        }
    }
}

// ---------------------------------------------------------------------------
// Launch
// ---------------------------------------------------------------------------
extern "C" void kernel_launch(void* const* d_in, const int* in_sizes, int n_in,
                              void* d_out, int out_size) {
    const float* x    = (const float*)d_in[0];
    const float* Wk   = (const float*)d_in[1];
    const float* Wr   = (const float*)d_in[2];
    const float* bias = (const float*)d_in[3];
    const float* Wd   = (const float*)d_in[4];
    const float* bd   = (const float*)d_in[5];
    float* out = (float*)d_out;

    const int smem_bytes = SMEM_U32 * (int)sizeof(uint32_t);   // 133280
    cudaFuncSetAttribute(lstm_fused, cudaFuncAttributeMaxDynamicSharedMemorySize,
                         smem_bytes);

    reset_kernel<<<64, 256>>>();
    lstm_fused<<<NCTA, NTHR, smem_bytes>>>(x, Wr, Wk, bias, Wd, bd, out);
}